// round 17
// baseline (speedup 1.0000x reference)
#include <cuda_runtime.h>
#include <cstdint>

// ---------------------------------------------------------------------------
// NeuralMMU: phys = pack26( (GELU(bits(va) @ W1 + b1) @ W2 + b2)[:26] > 0.5 )
//
// I/O MODEL (verified R15/R16): va=float64[B], out=float32[B], weights f32,
// sizes in elements. W1/W2 disambiguated on-device by variance; address
// format probed on-device (f64/i64/f32/i32). Probe now INLINED in the main
// kernel prologue (no separate launch).
//
// R17 (pipe rebalance; R16 was LSU-bound L1=80%, fma=48%):
//  - Bits 0..15: predicated packed adds of warp-UNIFORM W1 rows (FMA pipe,
//    broadcast LDS) instead of divergent nibble-LUT gathers (LSU pipe).
//  - Bits 16..30: nibble LUTs as before (3 x 16-entry + 1 x 8-entry tables).
//  - Layer 2 unchanged (13 packed logit pairs, ILP=2 addresses/thread).
//  - smem 79KB -> 50.3KB.
// ---------------------------------------------------------------------------

#define FMA2(d, a, b, c) asm("fma.rn.f32x2 %0, %1, %2, %3;" : "=l"(d) : "l"(a), "l"(b), "l"(c))
#define ADD2(d, a, b)    asm("add.rn.f32x2 %0, %1, %2;"     : "=l"(d) : "l"(a), "l"(b))
// If m != 0: p01 += wx, p23 += wy (packed f32x2, predicated — no divergence)
#define PADD2X2(p01, p23, wx, wy, m) \
    asm("{ .reg .pred p; setp.ne.u32 p, %4, 0;\n\t" \
        "@p add.rn.f32x2 %0, %0, %2;\n\t" \
        "@p add.rn.f32x2 %1, %1, %3; }" \
        : "+l"(p01), "+l"(p23) : "l"(wx), "l"(wy), "r"(m))

__device__ __forceinline__ unsigned long long pk(float lo, float hi) {
    unsigned long long r;
    asm("mov.b64 %0, {%1, %2};" : "=l"(r) : "f"(lo), "f"(hi));
    return r;
}
__device__ __forceinline__ void upk(unsigned long long v, float& lo, float& hi) {
    asm("mov.b64 {%0, %1}, %2;" : "=f"(lo), "=f"(hi) : "l"(v));
}

__device__ __forceinline__ float gelu_exact(float x) {
    return 0.5f * x * (1.0f + erff(x * 0.70710678118654752f));
}

// smem layout in float4/ulonglong2 units (16B):
//  [0, 1536)     LUT tables t=0..2 (bits 16..27): idx = t*512 + ig*16 + v
//  [1536, 1792)  LUT table  t=3   (bits 28..30): idx = 1536 + ig*8 + v
//  [1792, 2304)  W1F rows (bits 0..15): idx = ig*16 + bit
// then floats:
//  [9216, 12544) w2p float2[32][13][4]
//  [12544, ...)  sB2[26]
constexpr int LUT_F4    = 1792;
constexpr int W1F_F4    = 512;
constexpr int W2P_FOFF  = (LUT_F4 + W1F_F4) * 4;        // 9216 floats
constexpr int SMEM_W2P_F = 32 * 13 * 8;                 // 3328 floats
constexpr int SB2_FOFF  = W2P_FOFF + SMEM_W2P_F;        // 12544
constexpr int SMEM_TOTAL = (SB2_FOFF + 32) * 4;         // 50304 bytes

__global__ void __launch_bounds__(256, 2)
nmmu_kernel(const void* __restrict__ vaRaw,
            const float* __restrict__ A,    // first 8192-elt tensor
            const float* __restrict__ Bm,   // second 8192-elt tensor
            const float* __restrict__ b1g,
            const float* __restrict__ b2g,
            float* __restrict__ out,
            int B)
{
    extern __shared__ __align__(16) float smem[];
    ulonglong2* T2  = reinterpret_cast<ulonglong2*>(smem);
    ulonglong2* W1F = T2 + LUT_F4;
    float2*     w2p = reinterpret_cast<float2*>(smem + W2P_FOFF);
    ulonglong2* W2P = reinterpret_cast<ulonglong2*>(smem + W2P_FOFF);
    float*      sB2 = smem + SB2_FOFF;

    const int tid = threadIdx.x;
    const unsigned* vaw = (const unsigned*)vaRaw;

    // ---- Inline probe 1: W1/W2 by variance (1024 samples, ~11 sigma) ----
    {
        float sa = 0.f, sb = 0.f;
        for (int i = tid; i < 1024; i += 256) {
            const float x = A[i];  sa += x * x;
            const float y = Bm[i]; sb += y * y;
        }
        smem[tid] = sa; smem[256 + tid] = sb;
        __syncthreads();
        for (int s = 128; s > 0; s >>= 1) {
            if (tid < s) { smem[tid] += smem[tid + s];
                           smem[256 + tid] += smem[256 + tid + s]; }
            __syncthreads();
        }
    }
    const float ssqA = smem[0], ssqB = smem[256];
    __syncthreads();                       // done reading scratch
    const int w1f = (ssqA > ssqB) ? 1 : 0; // uniform across block
    const float* W1 = w1f ? A  : Bm;
    const float* W2 = w1f ? Bm : A;

    // ---- Inline probe 2: address format (uniform, every thread agrees) ----
    int amode;
    {
        unsigned odd_or = 0u; bool f64ok = true;
        #pragma unroll
        for (int k = 0; k < 8; k++) {
            const unsigned w = vaw[2 * k + 1];
            odd_or |= w;
            if (w != 0u) {
                const unsigned e = w >> 20;
                if (e < 0x3FFu || e > 0x41Fu) f64ok = false;
            }
        }
        if (odd_or == 0u)      amode = 1;          // raw int64
        else if (f64ok)        amode = 0;          // float64
        else {
            bool f32ok = true;
            #pragma unroll
            for (int k = 0; k < 8; k++) {
                const unsigned w = vaw[k];
                if (w < 0x3F800000u || w >= 0x4F800000u) f32ok = false;
            }
            amode = f32ok ? 2 : 3;
        }
    }

    // ---- Build LUT tables for bits 16..30 (b1 folded into t=0) ----
    for (int e = tid; e < LUT_F4; e += 256) {
        int ig, v, rbase, nb, foldb1;
        if (e < 1536) { const int t = e >> 9; ig = (e >> 4) & 31; v = e & 15;
                        rbase = 16 + 4 * t; nb = 4; foldb1 = (t == 0); }
        else          { const int r = e - 1536; ig = r >> 3; v = r & 7;
                        rbase = 28; nb = 3; foldb1 = 0; }
        float4 s;
        if (foldb1) s = *reinterpret_cast<const float4*>(&b1g[ig * 4]);
        else        s = make_float4(0.f, 0.f, 0.f, 0.f);
        for (int bbit = 0; bbit < nb; bbit++) {
            if (v & (1 << bbit)) {
                const float4 w = *reinterpret_cast<const float4*>(
                    &W1[(rbase + bbit) * 128 + ig * 4]);
                s.x += w.x; s.y += w.y; s.z += w.z; s.w += w.w;
            }
        }
        reinterpret_cast<float4*>(smem)[e] = s;
    }

    // ---- W1 rows for FMA bits 0..15: W1F[ig*16 + bit] ----
    for (int e = tid; e < W1F_F4; e += 256) {
        const int ig = e >> 4, bit = e & 15;
        reinterpret_cast<float4*>(smem)[LUT_F4 + e] =
            *reinterpret_cast<const float4*>(&W1[bit * 128 + ig * 4]);
    }

    // ---- Paired-j W2 ----
    for (int e = tid; e < 32 * 13 * 4; e += 256) {
        const int u  = e & 3;
        const int r  = e >> 2;
        const int p  = r % 13;
        const int ig = r / 13;
        const int ug = ig * 4 + u;
        w2p[e] = make_float2(W2[ug * 64 + 2 * p], W2[ug * 64 + 2 * p + 1]);
    }
    if (tid < 26) sB2[tid] = b2g[tid];
    __syncthreads();

    const double* vad = (const double*)vaRaw;
    const float*  vaf = (const float*)vaRaw;
    auto lda = [&](int idx) -> unsigned {
        if (amode == 0) return (unsigned)(long long)vad[idx];
        if (amode == 1) return vaw[(size_t)idx * 2];
        if (amode == 2) return (unsigned)vaf[idx];
        return vaw[idx];
    };

    const int half = (B + 1) >> 1;
    const int gs   = gridDim.x * blockDim.x;

    for (int i = blockIdx.x * blockDim.x + tid; i < half; i += gs) {
        const int  i0   = i;
        const int  i1   = i + half;
        const bool has1 = (i1 < B);

        const unsigned a0 = lda(i0);
        const unsigned a1 = has1 ? lda(i1) : a0;

        // LUT entry indices (within one ig-slice)
        const int o0A = (int)((a0 >> 16) & 15u);
        const int o1A = 512  + (int)((a0 >> 20) & 15u);
        const int o2A = 1024 + (int)((a0 >> 24) & 15u);
        const int o3A = (int)((a0 >> 28) & 7u);
        const int o0B = (int)((a1 >> 16) & 15u);
        const int o1B = 512  + (int)((a1 >> 20) & 15u);
        const int o2B = 1024 + (int)((a1 >> 24) & 15u);
        const int o3B = (int)((a1 >> 28) & 7u);

        unsigned long long acc0[13], acc1[13];
        #pragma unroll
        for (int p = 0; p < 13; p++) {
            const unsigned long long b = pk(sB2[2 * p], sB2[2 * p + 1]);
            acc0[p] = b; acc1[p] = b;
        }

        for (int ig = 0; ig < 32; ig++) {
            const ulonglong2* Tig  = T2 + ig * 16;        // tables t<3
            const ulonglong2* T3ig = T2 + 1536 + ig * 8;  // table t=3
            const ulonglong2* Wig  = W1F + ig * 16;       // FMA-bit rows

            // ---- layer 1: LUT part (bits 16..30), both addresses ----
            ulonglong2 e0 = Tig[o0A];
            unsigned long long pA01 = e0.x, pA23 = e0.y;
            ulonglong2 q;
            q = Tig[o1A];  ADD2(pA01, pA01, q.x); ADD2(pA23, pA23, q.y);
            q = Tig[o2A];  ADD2(pA01, pA01, q.x); ADD2(pA23, pA23, q.y);
            q = T3ig[o3A]; ADD2(pA01, pA01, q.x); ADD2(pA23, pA23, q.y);

            ulonglong2 e1 = Tig[o0B];
            unsigned long long pB01 = e1.x, pB23 = e1.y;
            q = Tig[o1B];  ADD2(pB01, pB01, q.x); ADD2(pB23, pB23, q.y);
            q = Tig[o2B];  ADD2(pB01, pB01, q.x); ADD2(pB23, pB23, q.y);
            q = T3ig[o3B]; ADD2(pB01, pB01, q.x); ADD2(pB23, pB23, q.y);

            // ---- layer 1: FMA part (bits 0..15), uniform weights ----
            #pragma unroll
            for (int bit = 0; bit < 16; bit++) {
                const ulonglong2 w = Wig[bit];
                PADD2X2(pA01, pA23, w.x, w.y, a0 & (1u << bit));
                PADD2X2(pB01, pB23, w.x, w.y, a1 & (1u << bit));
            }

            float xA0, xA1, xA2, xA3, xB0, xB1, xB2, xB3;
            upk(pA01, xA0, xA1); upk(pA23, xA2, xA3);
            upk(pB01, xB0, xB1); upk(pB23, xB2, xB3);

            const float hA0 = gelu_exact(xA0), hA1 = gelu_exact(xA1);
            const float hA2 = gelu_exact(xA2), hA3 = gelu_exact(xA3);
            const float hB0 = gelu_exact(xB0), hB1 = gelu_exact(xB1);
            const float hB2 = gelu_exact(xB2), hB3 = gelu_exact(xB3);

            const unsigned long long a0u0 = pk(hA0, hA0), a0u1 = pk(hA1, hA1);
            const unsigned long long a0u2 = pk(hA2, hA2), a0u3 = pk(hA3, hA3);
            const unsigned long long a1u0 = pk(hB0, hB0), a1u1 = pk(hB1, hB1);
            const unsigned long long a1u2 = pk(hB2, hB2), a1u3 = pk(hB3, hB3);

            // ---- layer 2: 13 packed logit pairs, weights shared ----
            #pragma unroll
            for (int p = 0; p < 13; p++) {
                const ulonglong2 wA = W2P[(ig * 13 + p) * 2];
                const ulonglong2 wB = W2P[(ig * 13 + p) * 2 + 1];
                FMA2(acc0[p], a0u0, wA.x, acc0[p]);
                FMA2(acc0[p], a0u1, wA.y, acc0[p]);
                FMA2(acc0[p], a0u2, wB.x, acc0[p]);
                FMA2(acc0[p], a0u3, wB.y, acc0[p]);
                FMA2(acc1[p], a1u0, wA.x, acc1[p]);
                FMA2(acc1[p], a1u1, wA.y, acc1[p]);
                FMA2(acc1[p], a1u2, wB.x, acc1[p]);
                FMA2(acc1[p], a1u3, wB.y, acc1[p]);
            }
        }

        unsigned phys0 = 0u, phys1 = 0u;
        #pragma unroll
        for (int p = 0; p < 13; p++) {
            float lo, hi;
            upk(acc0[p], lo, hi);
            if (lo > 0.5f) phys0 |= (1u << (2 * p));
            if (hi > 0.5f) phys0 |= (1u << (2 * p + 1));
            upk(acc1[p], lo, hi);
            if (lo > 0.5f) phys1 |= (1u << (2 * p));
            if (hi > 0.5f) phys1 |= (1u << (2 * p + 1));
        }

        out[i0] = (float)phys0;
        if (has1) out[i1] = (float)phys1;
    }
}

extern "C" void kernel_launch(void* const* d_in, const int* in_sizes, int n_in,
                              void* d_out, int out_size)
{
    const void* va = nullptr;
    const float *Am = nullptr, *Bm = nullptr, *b1 = nullptr, *b2 = nullptr;
    int B = 0;
    for (int i = 0; i < n_in; i++) {
        const int s = in_sizes[i];
        if (s == 128)       b1 = (const float*)d_in[i];
        else if (s == 64)   b2 = (const float*)d_in[i];
        else if (s == 8192) { if (!Am) Am = (const float*)d_in[i];
                              else     Bm = (const float*)d_in[i]; }
        else                { va = d_in[i]; B = s; }
    }
    if (!va || !Am || !Bm || !b1 || !b2 || B <= 0) return;

    cudaFuncSetAttribute(nmmu_kernel,
                         cudaFuncAttributeMaxDynamicSharedMemorySize, SMEM_TOTAL);

    // single launch (probes inlined); one wave: 2 CTAs/SM x 148 SMs
    nmmu_kernel<<<296, 256, SMEM_TOTAL>>>(va, Am, Bm, b1, b2,
                                          (float*)d_out, B);
}